// round 1
// baseline (speedup 1.0000x reference)
#include <cuda_runtime.h>

typedef unsigned long long u64;

#define N_NODES 100000
#define N_EDGES 1600000
#define D_IN    64
#define D_H     256
#define BN_EPS  1e-5f

// Scratch: h = x + sum_j x_j (init to x, then scatter-add). 25.6 MB device global.
__device__ __align__(16) float g_aggr[(size_t)N_NODES * D_IN];

// ---------------------------------------------------------------------------
// Kernel 1: aggr = x   (vectorized copy)
// ---------------------------------------------------------------------------
__global__ void k_init_aggr(const float* __restrict__ x) {
    int i = blockIdx.x * blockDim.x + threadIdx.x;
    if (i < N_NODES * (D_IN / 4)) {
        reinterpret_cast<float4*>(g_aggr)[i] =
            reinterpret_cast<const float4*>(x)[i];
    }
}

// ---------------------------------------------------------------------------
// Kernel 2: scatter-add  aggr[dst] += x[src]   (vector red.add.v4.f32)
// 16 threads per edge (one float4 column chunk each) -> coalesced row reads.
// ---------------------------------------------------------------------------
__global__ void k_scatter(const float* __restrict__ x, const int* __restrict__ ei) {
    int gid = blockIdx.x * blockDim.x + threadIdx.x;   // < 25.6M, fits int
    int e = gid >> 4;
    int c = gid & 15;
    if (e < N_EDGES) {
        int src = __ldg(ei + e);
        int dst = __ldg(ei + N_EDGES + e);
        float4 v = __ldg(reinterpret_cast<const float4*>(x) + (size_t)src * 16 + c);
        float* p = g_aggr + (size_t)dst * 64 + c * 4;
        asm volatile("red.global.add.v4.f32 [%0], {%1,%2,%3,%4};"
                     :: "l"(p), "f"(v.x), "f"(v.y), "f"(v.z), "f"(v.w)
                     : "memory");
    }
}

// ---------------------------------------------------------------------------
// Packed f32x2 helpers (Blackwell fma.rn.f32x2: 2 FMAs per instruction)
// ---------------------------------------------------------------------------
__device__ __forceinline__ u64 pack2(float lo, float hi) {
    u64 r; asm("mov.b64 %0, {%1, %2};" : "=l"(r) : "f"(lo), "f"(hi)); return r;
}
__device__ __forceinline__ u64 fma2(u64 a, u64 b, u64 c) {
    u64 d; asm("fma.rn.f32x2 %0, %1, %2, %3;" : "=l"(d) : "l"(a), "l"(b), "l"(c));
    return d;
}
__device__ __forceinline__ float2 unpack2(u64 v) {
    float2 r; asm("mov.b64 {%0, %1}, %2;" : "=f"(r.x), "=f"(r.y) : "l"(v)); return r;
}
__device__ __forceinline__ float comp(const float4& v, int k) {
    return k == 0 ? v.x : k == 1 ? v.y : k == 2 ? v.z : v.w;  // k compile-time after unroll
}

// ---------------------------------------------------------------------------
// Kernel 3: fused  relu(bn2(relu(bn1(h@W1+b1))@W2+b2))
// CTA tile: 64 nodes x 256 cols. 256 threads, 8x8 micro-tile per thread.
// SMEM: sA [64][64] h-tile, sB [32][256] weight chunk, sH [64][256] hidden.
// ---------------------------------------------------------------------------
#define SMEM_FLOATS (64*64 + 32*256 + 64*256)   // 28672 floats = 114688 B

__global__ __launch_bounds__(256, 2)
void k_mlp(const float* __restrict__ W1, const float* __restrict__ b1,
           const float* __restrict__ g1, const float* __restrict__ be1,
           const float* __restrict__ rm1, const float* __restrict__ rv1,
           const float* __restrict__ W2, const float* __restrict__ b2,
           const float* __restrict__ g2, const float* __restrict__ be2,
           const float* __restrict__ rm2, const float* __restrict__ rv2,
           float* __restrict__ out) {
    extern __shared__ float smem[];
    float* sA = smem;                // [64][64]
    float* sB = sA + 64 * 64;        // [32][256]
    float* sH = sB + 32 * 256;       // [64][256]

    const int t   = threadIdx.x;
    const int tm  = t >> 5;          // 0..7  (row group: rows tm*8 .. tm*8+7)
    const int tn  = t & 31;          // 0..31 (col group: cols tn*8 .. tn*8+7)
    const int row0 = blockIdx.x * 64;

    // ---- load h tile (g_aggr) into sA, row-major, zero-pad OOB rows ----
    {
        const float4* src = reinterpret_cast<const float4*>(g_aggr);
        float4* dst = reinterpret_cast<float4*>(sA);
        #pragma unroll
        for (int j = 0; j < 4; j++) {
            int i  = t + 256 * j;          // 0..1023
            int r  = i >> 4;               // 0..63
            int c4 = i & 15;
            float4 v = make_float4(0.f, 0.f, 0.f, 0.f);
            if (row0 + r < N_NODES)
                v = src[(size_t)(row0 + r) * 16 + c4];
            dst[r * 16 + c4] = v;
        }
    }

    u64 acc[8][4];
    #pragma unroll
    for (int i = 0; i < 8; i++)
        #pragma unroll
        for (int j = 0; j < 4; j++) acc[i][j] = 0ull;   // == {0.0f, 0.0f}

    // ================= GEMM1: [64x64] @ [64x256], K chunks of 32 =========
    for (int ch = 0; ch < 2; ch++) {
        __syncthreads();
        {   // stage W1 rows [ch*32, ch*32+32)
            const float4* w = reinterpret_cast<const float4*>(W1) + ch * 32 * 64;
            float4* d = reinterpret_cast<float4*>(sB);
            #pragma unroll
            for (int j = 0; j < 8; j++) d[t + 256 * j] = w[t + 256 * j];
        }
        __syncthreads();
        #pragma unroll
        for (int k4 = 0; k4 < 8; k4++) {
            float4 a4[8];
            #pragma unroll
            for (int i = 0; i < 8; i++)
                a4[i] = reinterpret_cast<const float4*>(sA)[(tm * 8 + i) * 16 + ch * 8 + k4];
            #pragma unroll
            for (int kk = 0; kk < 4; kk++) {
                const u64* brow = reinterpret_cast<const u64*>(sB + (k4 * 4 + kk) * 256) + tn * 4;
                u64 bb0 = brow[0], bb1 = brow[1], bb2 = brow[2], bb3 = brow[3];
                #pragma unroll
                for (int i = 0; i < 8; i++) {
                    float a = comp(a4[i], kk);
                    u64 aa = pack2(a, a);
                    acc[i][0] = fma2(aa, bb0, acc[i][0]);
                    acc[i][1] = fma2(aa, bb1, acc[i][1]);
                    acc[i][2] = fma2(aa, bb2, acc[i][2]);
                    acc[i][3] = fma2(aa, bb3, acc[i][3]);
                }
            }
        }
    }

    // ---- epilogue 1: BN1 + ReLU -> sH ----
    {
        float s1v[8], o1v[8];
        #pragma unroll
        for (int j = 0; j < 8; j++) {
            int n = tn * 8 + j;
            float s = g1[n] * rsqrtf(rv1[n] + BN_EPS);
            s1v[j] = s;
            o1v[j] = (b1[n] - rm1[n]) * s + be1[n];
        }
        #pragma unroll
        for (int i = 0; i < 8; i++) {
            float r[8];
            #pragma unroll
            for (int j = 0; j < 4; j++) {
                float2 p = unpack2(acc[i][j]);
                r[2 * j]     = fmaxf(p.x * s1v[2 * j]     + o1v[2 * j],     0.f);
                r[2 * j + 1] = fmaxf(p.y * s1v[2 * j + 1] + o1v[2 * j + 1], 0.f);
                acc[i][j] = 0ull;
            }
            float4* d = reinterpret_cast<float4*>(sH + (tm * 8 + i) * 256 + tn * 8);
            d[0] = make_float4(r[0], r[1], r[2], r[3]);
            d[1] = make_float4(r[4], r[5], r[6], r[7]);
        }
    }

    // ================= GEMM2: [64x256] @ [256x256], K chunks of 32 ========
    for (int ch = 0; ch < 8; ch++) {
        __syncthreads();
        {   // stage W2 rows [ch*32, ch*32+32)
            const float4* w = reinterpret_cast<const float4*>(W2) + ch * 32 * 64;
            float4* d = reinterpret_cast<float4*>(sB);
            #pragma unroll
            for (int j = 0; j < 8; j++) d[t + 256 * j] = w[t + 256 * j];
        }
        __syncthreads();
        #pragma unroll
        for (int k4 = 0; k4 < 8; k4++) {
            float4 a4[8];
            #pragma unroll
            for (int i = 0; i < 8; i++)
                a4[i] = reinterpret_cast<const float4*>(sH)[(tm * 8 + i) * 64 + ch * 8 + k4];
            #pragma unroll
            for (int kk = 0; kk < 4; kk++) {
                const u64* brow = reinterpret_cast<const u64*>(sB + (k4 * 4 + kk) * 256) + tn * 4;
                u64 bb0 = brow[0], bb1 = brow[1], bb2 = brow[2], bb3 = brow[3];
                #pragma unroll
                for (int i = 0; i < 8; i++) {
                    float a = comp(a4[i], kk);
                    u64 aa = pack2(a, a);
                    acc[i][0] = fma2(aa, bb0, acc[i][0]);
                    acc[i][1] = fma2(aa, bb1, acc[i][1]);
                    acc[i][2] = fma2(aa, bb2, acc[i][2]);
                    acc[i][3] = fma2(aa, bb3, acc[i][3]);
                }
            }
        }
    }

    // ---- epilogue 2: BN2 + ReLU -> out ----
    {
        float s2v[8], o2v[8];
        #pragma unroll
        for (int j = 0; j < 8; j++) {
            int n = tn * 8 + j;
            float s = g2[n] * rsqrtf(rv2[n] + BN_EPS);
            s2v[j] = s;
            o2v[j] = (b2[n] - rm2[n]) * s + be2[n];
        }
        #pragma unroll
        for (int i = 0; i < 8; i++) {
            int node = row0 + tm * 8 + i;
            if (node < N_NODES) {
                float r[8];
                #pragma unroll
                for (int j = 0; j < 4; j++) {
                    float2 p = unpack2(acc[i][j]);
                    r[2 * j]     = fmaxf(p.x * s2v[2 * j]     + o2v[2 * j],     0.f);
                    r[2 * j + 1] = fmaxf(p.y * s2v[2 * j + 1] + o2v[2 * j + 1], 0.f);
                }
                float4* d = reinterpret_cast<float4*>(out + (size_t)node * 256 + tn * 8);
                d[0] = make_float4(r[0], r[1], r[2], r[3]);
                d[1] = make_float4(r[4], r[5], r[6], r[7]);
            }
        }
    }
}

// ---------------------------------------------------------------------------
// Launch
// ---------------------------------------------------------------------------
extern "C" void kernel_launch(void* const* d_in, const int* in_sizes, int n_in,
                              void* d_out, int out_size) {
    const float* x   = (const float*)d_in[0];
    // d_in[1] = pos (unused)
    const int*   ei  = (const int*)  d_in[2];
    const float* W1  = (const float*)d_in[3];
    const float* b1  = (const float*)d_in[4];
    const float* g1  = (const float*)d_in[5];
    const float* be1 = (const float*)d_in[6];
    const float* rm1 = (const float*)d_in[7];
    const float* rv1 = (const float*)d_in[8];
    const float* W2  = (const float*)d_in[9];
    const float* b2  = (const float*)d_in[10];
    const float* g2  = (const float*)d_in[11];
    const float* be2 = (const float*)d_in[12];
    const float* rm2 = (const float*)d_in[13];
    const float* rv2 = (const float*)d_in[14];
    float* out = (float*)d_out;

    // 1) aggr = x
    {
        int total = N_NODES * (D_IN / 4);
        k_init_aggr<<<(total + 255) / 256, 256>>>(x);
    }
    // 2) aggr[dst] += x[src]
    {
        long long total = (long long)N_EDGES * 16;
        int blocks = (int)((total + 255) / 256);
        k_scatter<<<blocks, 256>>>(x, ei);
    }
    // 3) fused MLP
    {
        static bool attr_set = false;
        size_t smem_bytes = SMEM_FLOATS * sizeof(float);
        cudaFuncSetAttribute(k_mlp, cudaFuncAttributeMaxDynamicSharedMemorySize,
                             (int)smem_bytes);
        int blocks = (N_NODES + 63) / 64;   // 1563
        k_mlp<<<blocks, 256, smem_bytes>>>(W1, b1, g1, be1, rm1, rv1,
                                           W2, b2, g2, be2, rm2, rv2, out);
        (void)attr_set;
    }
    (void)in_sizes; (void)n_in; (void)out_size;
}

// round 3
// speedup vs baseline: 1.7956x; 1.7956x over previous
#include <cuda_runtime.h>
#include <cuda_bf16.h>
#include <stdint.h>
#include <string.h>

#define N_NODES 100000
#define N_EDGES 1600000
#define BN_EPS  1e-5f

// ---------------------------------------------------------------------------
// Device scratch
// ---------------------------------------------------------------------------
__device__ __align__(16) float g_aggr[(size_t)N_NODES * 64];
// Weight image: 10 K-chunks of 32 (chunks 0-1 = W1, 2-9 = W2).
// Chunk c @ c*40960: hi plane [256 n][40 k] bf16 (20480 B), lo plane @ +20480.
__device__ __align__(16) unsigned char g_Wimg[409600];
// folded BN: y = v*s + o, then ReLU
__device__ float g_s1[256], g_o1[256], g_s2[256], g_o2[256];

// ---------------------------------------------------------------------------
// Kernel 1: aggr = x
// ---------------------------------------------------------------------------
__global__ void k_init_aggr(const float* __restrict__ x) {
    int i = blockIdx.x * blockDim.x + threadIdx.x;
    if (i < N_NODES * 16) {
        reinterpret_cast<float4*>(g_aggr)[i] =
            reinterpret_cast<const float4*>(x)[i];
    }
}

// ---------------------------------------------------------------------------
// Kernel 2: scatter-add  aggr[dst] += x[src]  (red.global.add.v4.f32)
// ---------------------------------------------------------------------------
__global__ void k_scatter(const float* __restrict__ x, const int* __restrict__ ei) {
    int gid = blockIdx.x * blockDim.x + threadIdx.x;
    int e = gid >> 4;
    int c = gid & 15;
    if (e < N_EDGES) {
        int src = __ldg(ei + e);
        int dst = __ldg(ei + N_EDGES + e);
        float4 v = __ldg(reinterpret_cast<const float4*>(x) + (size_t)src * 16 + c);
        float* p = g_aggr + (size_t)dst * 64 + c * 4;
        asm volatile("red.global.add.v4.f32 [%0], {%1,%2,%3,%4};"
                     :: "l"(p), "f"(v.x), "f"(v.y), "f"(v.z), "f"(v.w)
                     : "memory");
    }
}

// ---------------------------------------------------------------------------
// Prep: weights -> bf16 hi/lo [n][k]-padded chunk images; fold BN
// ---------------------------------------------------------------------------
__global__ void k_prep(const float* __restrict__ W1, const float* __restrict__ W2,
    const float* __restrict__ b1, const float* __restrict__ g1, const float* __restrict__ be1,
    const float* __restrict__ rm1, const float* __restrict__ rv1,
    const float* __restrict__ b2, const float* __restrict__ g2, const float* __restrict__ be2,
    const float* __restrict__ rm2, const float* __restrict__ rv2)
{
    int t = blockIdx.x * 256 + threadIdx.x;
    if (t < 81920) {
        int ci = t >> 13;          // chunk 0..9
        int r  = t & 8191;
        int n  = r >> 5;           // 0..255
        int kl = r & 31;           // 0..31
        float v;
        if (ci < 2) v = W1[(size_t)(ci * 32 + kl) * 256 + n];
        else        v = W2[(size_t)((ci - 2) * 32 + kl) * 256 + n];
        __nv_bfloat16 h = __float2bfloat16(v);
        __nv_bfloat16 l = __float2bfloat16(v - __bfloat162float(h));
        unsigned char* base = g_Wimg + (size_t)ci * 40960;
        *(__nv_bfloat16*)(base + n * 80 + kl * 2)         = h;
        *(__nv_bfloat16*)(base + 20480 + n * 80 + kl * 2) = l;
    } else if (t < 82432) {
        int i = t - 81920;
        int n = i & 255;
        if (i < 256) { float s = g1[n] * rsqrtf(rv1[n] + BN_EPS); g_s1[n] = s; g_o1[n] = (b1[n] - rm1[n]) * s + be1[n]; }
        else         { float s = g2[n] * rsqrtf(rv2[n] + BN_EPS); g_s2[n] = s; g_o2[n] = (b2[n] - rm2[n]) * s + be2[n]; }
    }
}

// ---------------------------------------------------------------------------
// PTX helpers (all arch-agnostic: sm_80+ features only)
// ---------------------------------------------------------------------------
__device__ __forceinline__ uint32_t s2u(const void* p) {
    uint32_t a;
    asm("{ .reg .u64 t; cvta.to.shared.u64 t, %1; cvt.u32.u64 %0, t; }" : "=r"(a) : "l"(p));
    return a;
}
__device__ __forceinline__ void ldm4(uint32_t* r, uint32_t addr) {
    asm volatile("ldmatrix.sync.aligned.m8n8.x4.shared.b16 {%0,%1,%2,%3}, [%4];"
                 : "=r"(r[0]), "=r"(r[1]), "=r"(r[2]), "=r"(r[3]) : "r"(addr));
}
__device__ __forceinline__ void mma_bf16(float* c, const uint32_t* a, uint32_t b0, uint32_t b1) {
    asm volatile(
        "mma.sync.aligned.m16n8k16.row.col.f32.bf16.bf16.f32 "
        "{%0,%1,%2,%3}, {%4,%5,%6,%7}, {%8,%9}, {%0,%1,%2,%3};"
        : "+f"(c[0]), "+f"(c[1]), "+f"(c[2]), "+f"(c[3])
        : "r"(a[0]), "r"(a[1]), "r"(a[2]), "r"(a[3]), "r"(b0), "r"(b1));
}
__device__ __forceinline__ void cpa16(uint32_t s, const void* g) {
    asm volatile("cp.async.cg.shared.global [%0], [%1], 16;" :: "r"(s), "l"(g));
}
#define CP_COMMIT() asm volatile("cp.async.commit_group;" ::: "memory")

__device__ __forceinline__ void split_pack(float a, float b, uint32_t& hi, uint32_t& lo) {
    __nv_bfloat16 ah = __float2bfloat16(a), bh = __float2bfloat16(b);
    float ar = a - __bfloat162float(ah);
    float br = b - __bfloat162float(bh);
    __nv_bfloat162 hp = __halves2bfloat162(ah, bh);   // low half = a
    __nv_bfloat162 lp = __floats2bfloat162_rn(ar, br);
    memcpy(&hi, &hp, 4);
    memcpy(&lo, &lp, 4);
}

// ---------------------------------------------------------------------------
// Kernel 3: bf16 mma.sync MLP. CTA = 128 nodes x 256 cols, 512 threads.
// SMEM layout (byte offsets from 1KB-aligned base):
//   [0, 135168)         H region: layer1 A (hi@0 [128][72], lo@18432),
//                       later layer2 A = H1 (hi@0 [128][264], lo@67584)
//   [135168, 176128)    B buf0: hi [256][40] @+0, lo @+20480
//   [176128, 217088)    B buf1
// ---------------------------------------------------------------------------
#define OFF_B0   135168
#define BUF_SZ   40960
#define A1LO     18432
#define H1LO     67584
#define SMEM_REQ (217088 + 1024)

__global__ __launch_bounds__(512, 1) void k_mlp3(float* __restrict__ out) {
    extern __shared__ unsigned char dyn[];
    uint32_t raw = s2u(dyn);
    uint32_t sb  = (raw + 1023u) & ~1023u;
    unsigned char* sp = dyn + (sb - raw);   // generic pointer to same base

    const int tid  = threadIdx.x;
    const int lane = tid & 31;
    const int w    = tid >> 5;
    const int m_w  = (w >> 2) * 32;
    const int n_w  = (w & 3) * 64;
    const int lr   = lane & 7, lsel = lane >> 3;
    const int arow = lr + (lsel & 1) * 8, acol8 = (lsel >> 1) * 8;
    const int brow = lr + (lsel >> 1) * 8, bcol8 = (lsel & 1) * 8;
    const int gid  = lane >> 2, tg2 = (lane & 3) * 2;
    const int row0 = blockIdx.x * 128;

    // ---- prefetch weight chunks 0,1 ----
    #pragma unroll
    for (int j = 0; j < 5; j++)
        cpa16(sb + OFF_B0 + (tid + 512 * j) * 16, g_Wimg + (tid + 512 * j) * 16);
    CP_COMMIT();
    #pragma unroll
    for (int j = 0; j < 5; j++)
        cpa16(sb + OFF_B0 + BUF_SZ + (tid + 512 * j) * 16, g_Wimg + BUF_SZ + (tid + 512 * j) * 16);
    CP_COMMIT();

    // ---- load h tile [128][64] f32 -> bf16 hi/lo A1 (stride 72) ----
    {
        int rr = tid >> 2, q = tid & 3;
        float4 f[4];
        #pragma unroll
        for (int i = 0; i < 4; i++) {
            f[i] = make_float4(0.f, 0.f, 0.f, 0.f);
            if (row0 + rr < N_NODES)
                f[i] = ((const float4*)g_aggr)[(size_t)(row0 + rr) * 16 + q * 4 + i];
        }
        uint32_t hi[8], lo[8];
        #pragma unroll
        for (int i = 0; i < 4; i++) {
            split_pack(f[i].x, f[i].y, hi[2 * i],     lo[2 * i]);
            split_pack(f[i].z, f[i].w, hi[2 * i + 1], lo[2 * i + 1]);
        }
        int off = rr * 144 + q * 32;
        *(uint4*)(sp + off)            = ((uint4*)hi)[0];
        *(uint4*)(sp + off + 16)       = ((uint4*)hi)[1];
        *(uint4*)(sp + A1LO + off)     = ((uint4*)lo)[0];
        *(uint4*)(sp + A1LO + off + 16) = ((uint4*)lo)[1];
    }

    float acc[2][8][4];
    #pragma unroll
    for (int a = 0; a < 2; a++)
        #pragma unroll
        for (int b = 0; b < 8; b++)
            #pragma unroll
            for (int cq = 0; cq < 4; cq++) acc[a][b][cq] = 0.f;

    __syncthreads();   // A1 ready

    for (int i = 0; i < 10; i++) {
        if (i == 9) asm volatile("cp.async.wait_group 0;" ::: "memory");
        else        asm volatile("cp.async.wait_group 1;" ::: "memory");
        __syncthreads();   // chunk i visible to all; prev buffer fully consumed

        const bool l1 = (i < 2);
        const uint32_t a_hi = sb;
        const uint32_t a_lo = sb + (l1 ? A1LO : H1LO);
        const int S   = l1 ? 72 : 264;
        const int kA0 = l1 ? i * 32 : (i - 2) * 32;
        const uint32_t bbuf = sb + OFF_B0 + (i & 1) * BUF_SZ;

        #pragma unroll
        for (int step = 0; step < 2; step++) {
            const int kA = kA0 + step * 16;
            const int kB = step * 16;
            uint32_t Ah[2][4], Al[2][4], Bb[4][4];
            #pragma unroll
            for (int mt = 0; mt < 2; mt++)
                ldm4(Ah[mt], a_hi + ((m_w + mt * 16 + arow) * S + kA + acol8) * 2);
            #pragma unroll
            for (int np = 0; np < 4; np++)
                ldm4(Bb[np], bbuf + ((n_w + np * 16 + brow) * 40 + kB + bcol8) * 2);
            // hi * hi
            #pragma unroll
            for (int mt = 0; mt < 2; mt++)
                #pragma unroll
                for (int np = 0; np < 4; np++) {
                    mma_bf16(acc[mt][np * 2],     Ah[mt], Bb[np][0], Bb[np][1]);
                    mma_bf16(acc[mt][np * 2 + 1], Ah[mt], Bb[np][2], Bb[np][3]);
                }
            // lo * hi
            #pragma unroll
            for (int mt = 0; mt < 2; mt++)
                ldm4(Al[mt], a_lo + ((m_w + mt * 16 + arow) * S + kA + acol8) * 2);
            #pragma unroll
            for (int mt = 0; mt < 2; mt++)
                #pragma unroll
                for (int np = 0; np < 4; np++) {
                    mma_bf16(acc[mt][np * 2],     Al[mt], Bb[np][0], Bb[np][1]);
                    mma_bf16(acc[mt][np * 2 + 1], Al[mt], Bb[np][2], Bb[np][3]);
                }
            // hi * lo
            #pragma unroll
            for (int np = 0; np < 4; np++)
                ldm4(Bb[np], bbuf + 20480 + ((n_w + np * 16 + brow) * 40 + kB + bcol8) * 2);
            #pragma unroll
            for (int mt = 0; mt < 2; mt++)
                #pragma unroll
                for (int np = 0; np < 4; np++) {
                    mma_bf16(acc[mt][np * 2],     Ah[mt], Bb[np][0], Bb[np][1]);
                    mma_bf16(acc[mt][np * 2 + 1], Ah[mt], Bb[np][2], Bb[np][3]);
                }
        }

        __syncthreads();   // all warps done with buffer (i&1)

        if (i < 8) {       // prefetch chunk i+2 into freed buffer
            const unsigned char* g = g_Wimg + (size_t)(i + 2) * BUF_SZ;
            uint32_t s = sb + OFF_B0 + (i & 1) * BUF_SZ;
            #pragma unroll
            for (int j = 0; j < 5; j++)
                cpa16(s + (tid + 512 * j) * 16, g + (tid + 512 * j) * 16);
            CP_COMMIT();
        }

        if (i == 1) {
            // ---- epilogue 1: BN1 + ReLU -> H1 hi/lo (stride 264), reset acc ----
            #pragma unroll
            for (int nt = 0; nt < 8; nt++) {
                int col = n_w + nt * 8 + tg2;
                float2 s = *(const float2*)(g_s1 + col);
                float2 o = *(const float2*)(g_o1 + col);
                #pragma unroll
                for (int mt = 0; mt < 2; mt++) {
                    float* c = acc[mt][nt];
                    float v0 = fmaxf(c[0] * s.x + o.x, 0.f);
                    float v1 = fmaxf(c[1] * s.y + o.y, 0.f);
                    float v2 = fmaxf(c[2] * s.x + o.x, 0.f);
                    float v3 = fmaxf(c[3] * s.y + o.y, 0.f);
                    uint32_t h0, l0, h1, l1r;
                    split_pack(v0, v1, h0, l0);
                    split_pack(v2, v3, h1, l1r);
                    int r0 = m_w + mt * 16 + gid;
                    int o0 = (r0 * 264 + col) * 2;
                    int o1 = ((r0 + 8) * 264 + col) * 2;
                    *(uint32_t*)(sp + o0)        = h0;
                    *(uint32_t*)(sp + H1LO + o0) = l0;
                    *(uint32_t*)(sp + o1)        = h1;
                    *(uint32_t*)(sp + H1LO + o1) = l1r;
                    c[0] = c[1] = c[2] = c[3] = 0.f;
                }
            }
            // visibility handled by the syncthreads at top of i==2
        }
    }

    // ---- epilogue 2: BN2 + ReLU -> out ----
    #pragma unroll
    for (int nt = 0; nt < 8; nt++) {
        int col = n_w + nt * 8 + tg2;
        float2 s = *(const float2*)(g_s2 + col);
        float2 o = *(const float2*)(g_o2 + col);
        #pragma unroll
        for (int mt = 0; mt < 2; mt++) {
            float* c = acc[mt][nt];
            int r0 = row0 + m_w + mt * 16 + gid;
            if (r0 < N_NODES) {
                float2 v = make_float2(fmaxf(c[0] * s.x + o.x, 0.f),
                                       fmaxf(c[1] * s.y + o.y, 0.f));
                *(float2*)(out + (size_t)r0 * 256 + col) = v;
            }
            if (r0 + 8 < N_NODES) {
                float2 v = make_float2(fmaxf(c[2] * s.x + o.x, 0.f),
                                       fmaxf(c[3] * s.y + o.y, 0.f));
                *(float2*)(out + (size_t)(r0 + 8) * 256 + col) = v;
            }
        }
    }
}

// ---------------------------------------------------------------------------
// Launch
// ---------------------------------------------------------------------------
extern "C" void kernel_launch(void* const* d_in, const int* in_sizes, int n_in,
                              void* d_out, int out_size) {
    const float* x   = (const float*)d_in[0];
    const int*   ei  = (const int*)  d_in[2];
    const float* W1  = (const float*)d_in[3];
    const float* b1  = (const float*)d_in[4];
    const float* g1  = (const float*)d_in[5];
    const float* be1 = (const float*)d_in[6];
    const float* rm1 = (const float*)d_in[7];
    const float* rv1 = (const float*)d_in[8];
    const float* W2  = (const float*)d_in[9];
    const float* b2  = (const float*)d_in[10];
    const float* g2  = (const float*)d_in[11];
    const float* be2 = (const float*)d_in[12];
    const float* rm2 = (const float*)d_in[13];
    const float* rv2 = (const float*)d_in[14];
    float* out = (float*)d_out;

    k_init_aggr<<<(N_NODES * 16 + 255) / 256, 256>>>(x);

    {
        long long total = (long long)N_EDGES * 16;
        k_scatter<<<(int)((total + 255) / 256), 256>>>(x, ei);
    }

    k_prep<<<322, 256>>>(W1, W2, b1, g1, be1, rm1, rv1, b2, g2, be2, rm2, rv2);

    {
        cudaFuncSetAttribute(k_mlp3, cudaFuncAttributeMaxDynamicSharedMemorySize,
                             SMEM_REQ);
        int blocks = (N_NODES + 127) / 128;   // 782
        k_mlp3<<<blocks, 512, SMEM_REQ>>>(out);
    }
    (void)in_sizes; (void)n_in; (void)out_size;
}